// round 10
// baseline (speedup 1.0000x reference)
#include <cuda_runtime.h>
#include <cstdint>

#define BB 8
#define NN 1024
#define LL 16
#define DD 256
#define HH 4
#define DHH 64
#define NLAYERS 2

// ---------------- scratch (global __device__ arrays; no allocs) ----------------
__device__ float g_hA[BB * NN * DD];
__device__ float g_hB[BB * NN * DD];
__device__ float g_Wh[BB * NN * DD];
__device__ float g_P[BB * HH * NN];
__device__ float g_Q[BB * HH * NN];
__device__ float g_R[BB * HH * NN];
__device__ float g_S[BB * HH * NN];
__device__ unsigned g_mask[BB * NN * (NN / 32)];

// ---------------- kernel 0: node features = mean of token embeddings ----------------
__global__ __launch_bounds__(256) void k_gather(const int* __restrict__ nodes,
                                                const float* __restrict__ emb,
                                                float* __restrict__ out) {
    int row = blockIdx.x;              // b*N + n
    int t = threadIdx.x;               // 0..255 = feature dim
    __shared__ int idx[LL];
    if (t < LL) idx[t] = nodes[(size_t)row * LL + t];
    __syncthreads();
    float acc = 0.f;
#pragma unroll
    for (int l = 0; l < LL; ++l)
        acc += emb[(size_t)idx[l] * DD + t];
    out[(size_t)row * DD + t] = acc * (1.0f / (float)LL);
}

// ---------------- kernel 1: adjacency (+self loop) -> bitmask ----------------
__global__ __launch_bounds__(256) void k_mask(const int* __restrict__ adj,
                                              unsigned* __restrict__ mask) {
    int gt = blockIdx.x * blockDim.x + threadIdx.x;
    int gw = gt >> 5;                  // word id in [0, B*N*32)
    int lane = gt & 31;
    int row = gw >> 5;                 // b*N + n
    int word = gw & 31;
    int n = row & (NN - 1);
    int m = word * 32 + lane;
    int v = adj[(size_t)row * NN + m];
    bool bit = (v != 0) || (m == n);
    unsigned w = __ballot_sync(0xffffffffu, bit);
    if (lane == 0) mask[gw] = w;
}

// ---------------- kernel 2: Wh = h @ W  (per layer) ----------------
// Wh layout: [b][n][c] with c = h*64+k (matches h_cat layout).
__global__ __launch_bounds__(256) void k_gemm(const float* __restrict__ h,
                                              const float* __restrict__ Wl,  // [H][D][DH]
                                              float* __restrict__ Wh) {
    __shared__ float hs[16][32];
    __shared__ float ws[32][256];
    int t = threadIdx.x;
    int row0 = blockIdx.x * 16;
    int c0 = (t & 63) * 4;
    int r0 = (t >> 6) * 4;
    float acc[4][4] = {};

    for (int d0 = 0; d0 < DD; d0 += 32) {
        {
            int e = t;
            hs[e >> 5][e & 31] = h[(size_t)(row0 + (e >> 5)) * DD + d0 + (e & 31)];
            e = t + 256;
            hs[e >> 5][e & 31] = h[(size_t)(row0 + (e >> 5)) * DD + d0 + (e & 31)];
        }
#pragma unroll
        for (int q = 0; q < 32; ++q) {
            int c = t;                 // dd = q, c = t (coalesced)
            int hh = c >> 6, k = c & 63;
            ws[q][c] = Wl[((size_t)hh * DD + (d0 + q)) * DHH + k];
        }
        __syncthreads();
#pragma unroll
        for (int dd = 0; dd < 32; ++dd) {
            float a0 = hs[r0 + 0][dd], a1 = hs[r0 + 1][dd];
            float a2 = hs[r0 + 2][dd], a3 = hs[r0 + 3][dd];
            float b0 = ws[dd][c0 + 0], b1 = ws[dd][c0 + 1];
            float b2 = ws[dd][c0 + 2], b3 = ws[dd][c0 + 3];
            acc[0][0] += a0 * b0; acc[0][1] += a0 * b1; acc[0][2] += a0 * b2; acc[0][3] += a0 * b3;
            acc[1][0] += a1 * b0; acc[1][1] += a1 * b1; acc[1][2] += a1 * b2; acc[1][3] += a1 * b3;
            acc[2][0] += a2 * b0; acc[2][1] += a2 * b1; acc[2][2] += a2 * b2; acc[2][3] += a2 * b3;
            acc[3][0] += a3 * b0; acc[3][1] += a3 * b1; acc[3][2] += a3 * b2; acc[3][3] += a3 * b3;
        }
        __syncthreads();
    }
#pragma unroll
    for (int i = 0; i < 4; ++i)
#pragma unroll
        for (int j = 0; j < 4; ++j)
            Wh[(size_t)(row0 + r0 + i) * DD + c0 + j] = acc[i][j];
}

// ---------------- kernel 3: src/dst dots + factorized exps ----------------
// P=exp(src), R=exp(0.2 src), Q=exp(dst), S=exp(0.2 dst), indexed [b][h][n].
__global__ __launch_bounds__(256) void k_srcdst(const float* __restrict__ Wh,
                                                const float* __restrict__ asrc,  // [H][DH]
                                                const float* __restrict__ adst,
                                                float* __restrict__ P, float* __restrict__ Q,
                                                float* __restrict__ R, float* __restrict__ S) {
    int gt = blockIdx.x * blockDim.x + threadIdx.x;
    int g = gt >> 5;                   // warp id = (b*H + h)*N + n
    int lane = gt & 31;
    int n = g & (NN - 1);
    int h = (g >> 10) & 3;
    int b = g >> 12;
    const float* whrow = Wh + ((size_t)(b * NN + n)) * DD + h * DHH;
    float x0 = whrow[lane], x1 = whrow[lane + 32];
    float s = x0 * asrc[h * DHH + lane] + x1 * asrc[h * DHH + lane + 32];
    float d = x0 * adst[h * DHH + lane] + x1 * adst[h * DHH + lane + 32];
#pragma unroll
    for (int o = 16; o; o >>= 1) {
        s += __shfl_down_sync(0xffffffffu, s, o);
        d += __shfl_down_sync(0xffffffffu, d, o);
    }
    if (lane == 0) {
        P[g] = __expf(s);
        R[g] = __expf(0.2f * s);
        Q[g] = __expf(d);
        S[g] = __expf(0.2f * d);
    }
}

// ---------------- kernel 4: fused masked-softmax attention + residual + LN ----------------
// CTA: 16 query rows, all 4 heads, all 256 output cols. m tiled by 32.
__global__ __launch_bounds__(256) void k_attn(const float* __restrict__ hin,
                                              const float* __restrict__ Wh,
                                              const float* __restrict__ P,
                                              const float* __restrict__ Qv,
                                              const float* __restrict__ R,
                                              const float* __restrict__ Sv,
                                              const unsigned* __restrict__ mask,
                                              const float* __restrict__ lns,
                                              const float* __restrict__ lnb,
                                              float* __restrict__ out) {
    __shared__ union {
        float whs[32][256];            // Wh m-tile (32 KB), reused as ybuf after m-loop
        float ybuf[16][256];
    } u;
    __shared__ float wsh[4][16][33];   // scores w[h][n][m_local], padded
    __shared__ float Ps[4][16], Rs[4][16];
    __shared__ float Qs[4][32], Ss[4][32];
    __shared__ unsigned mw[16];
    __shared__ float zpart[4][4][16];  // [mgroup][h][n]
    __shared__ float zs[4][16];

    int t = threadIdx.x;
    int b = blockIdx.x >> 6;           // 64 tiles per batch
    int row0 = (blockIdx.x & 63) * 16;

    // per-row P/R (once)
    if (t < 64) {
        int h = t >> 4, n = t & 15;
        int g = (b * HH + h) * NN + row0 + n;
        Ps[h][n] = P[g];
        Rs[h][n] = R[g];
    }

    // phase-A identity: (h, n) pair + m-subgroup
    int pa_h = (t >> 4) & 3, pa_n = t & 15, mg = t >> 6;
    float zacc = 0.f;
    // phase-B identity: 4 rows x 4 cols per thread
    int c0 = (t & 63) * 4, r0 = (t >> 6) * 4, hb = c0 >> 6;
    float acc[4][4] = {};

    for (int m0 = 0; m0 < NN; m0 += 32) {
        // stage Wh tile: 32 rows x 256 cols
#pragma unroll
        for (int q = 0; q < 32; ++q)
            u.whs[q][t] = Wh[((size_t)(b * NN + m0 + q)) * DD + t];
        // stage Q/S for this m tile
        if (t < 128) {
            int h = t >> 5, mm = t & 31;
            Qs[h][mm] = Qv[(b * HH + h) * NN + m0 + mm];
        } else {
            int tt = t - 128;
            int h = tt >> 5, mm = tt & 31;
            Ss[h][mm] = Sv[(b * HH + h) * NN + m0 + mm];
        }
        if (t < 16) mw[t] = mask[((size_t)(b * NN + row0 + t)) * 32 + (m0 >> 5)];
        __syncthreads();

        // phase A: scores w = mask * (P*Q >= 1 ? P*Q : R*S)
        {
            float pn = Ps[pa_h][pa_n], rn = Rs[pa_h][pa_n];
            unsigned mwn = mw[pa_n];
#pragma unroll
            for (int j = 0; j < 8; ++j) {
                int ml = mg * 8 + j;
                float pq = pn * Qs[pa_h][ml];
                float w = (pq >= 1.0f) ? pq : rn * Ss[pa_h][ml];
                w = ((mwn >> ml) & 1u) ? w : 0.f;
                zacc += w;
                wsh[pa_h][pa_n][ml] = w;
            }
        }
        __syncthreads();

        // phase B: acc += w @ Wh_tile  (4x4 register tile)
#pragma unroll
        for (int mm = 0; mm < 32; ++mm) {
            float w0 = wsh[hb][r0 + 0][mm];
            float w1 = wsh[hb][r0 + 1][mm];
            float w2 = wsh[hb][r0 + 2][mm];
            float w3 = wsh[hb][r0 + 3][mm];
            float4 bv = *(const float4*)&u.whs[mm][c0];
            acc[0][0] += w0 * bv.x; acc[0][1] += w0 * bv.y; acc[0][2] += w0 * bv.z; acc[0][3] += w0 * bv.w;
            acc[1][0] += w1 * bv.x; acc[1][1] += w1 * bv.y; acc[1][2] += w1 * bv.z; acc[1][3] += w1 * bv.w;
            acc[2][0] += w2 * bv.x; acc[2][1] += w2 * bv.y; acc[2][2] += w2 * bv.z; acc[2][3] += w2 * bv.w;
            acc[3][0] += w3 * bv.x; acc[3][1] += w3 * bv.y; acc[3][2] += w3 * bv.z; acc[3][3] += w3 * bv.w;
        }
        __syncthreads();
    }

    // reduce z partials (4 m-subgroups per (h,n))
    zpart[mg][pa_h][pa_n] = zacc;
    __syncthreads();
    if (t < 64) {
        int h = t >> 4, n = t & 15;
        zs[h][n] = zpart[0][h][n] + zpart[1][h][n] + zpart[2][h][n] + zpart[3][h][n];
    }
    __syncthreads();

    // epilogue: y = h_in + h_prime/z  -> smem
#pragma unroll
    for (int i = 0; i < 4; ++i) {
        float zinv = 1.0f / zs[hb][r0 + i];
        int r = r0 + i;
#pragma unroll
        for (int j = 0; j < 4; ++j) {
            int c = c0 + j;
            u.ybuf[r][c] = hin[((size_t)(b * NN + row0 + r)) * DD + c] + acc[i][j] * zinv;
        }
    }
    __syncthreads();

    // layernorm: 8 warps x 2 rows each
    int wid = t >> 5, lane = t & 31;
#pragma unroll
    for (int rr = 0; rr < 2; ++rr) {
        int r = wid * 2 + rr;
        float sum = 0.f, sq = 0.f;
        float vals[8];
#pragma unroll
        for (int q = 0; q < 8; ++q) {
            float v = u.ybuf[r][lane + q * 32];
            vals[q] = v;
            sum += v;
            sq += v * v;
        }
#pragma unroll
        for (int o = 16; o; o >>= 1) {
            sum += __shfl_xor_sync(0xffffffffu, sum, o);
            sq += __shfl_xor_sync(0xffffffffu, sq, o);
        }
        float mu = sum * (1.0f / (float)DD);
        float var = sq * (1.0f / (float)DD) - mu * mu;
        float rstd = rsqrtf(var + 1e-5f);
#pragma unroll
        for (int q = 0; q < 8; ++q) {
            int c = lane + q * 32;
            out[((size_t)(b * NN + row0 + r)) * DD + c] = (vals[q] - mu) * rstd * lns[c] + lnb[c];
        }
    }
}

// ---------------- tail: cfg_len passthrough as float ----------------
__global__ void k_tail(const int* __restrict__ clen, float* __restrict__ out) {
    int t = threadIdx.x;
    if (t < BB) out[(size_t)BB * NN * DD + t] = (float)clen[t];
}

// ---------------- host ----------------
static void* sym_addr_hA() { void* p; cudaGetSymbolAddress(&p, g_hA); return p; }
static void* sym_addr_hB() { void* p; cudaGetSymbolAddress(&p, g_hB); return p; }
static void* sym_addr_Wh() { void* p; cudaGetSymbolAddress(&p, g_Wh); return p; }
static void* sym_addr_P()  { void* p; cudaGetSymbolAddress(&p, g_P);  return p; }
static void* sym_addr_Q()  { void* p; cudaGetSymbolAddress(&p, g_Q);  return p; }
static void* sym_addr_R()  { void* p; cudaGetSymbolAddress(&p, g_R);  return p; }
static void* sym_addr_S()  { void* p; cudaGetSymbolAddress(&p, g_S);  return p; }
static void* sym_addr_mask() { void* p; cudaGetSymbolAddress(&p, g_mask); return p; }

extern "C" void kernel_launch(void* const* d_in, const int* in_sizes, int n_in,
                              void* d_out, int out_size) {
    const int*   adj   = (const int*)d_in[0];
    const int*   nodes = (const int*)d_in[1];
    const int*   clen  = (const int*)d_in[2];
    const float* emb   = (const float*)d_in[3];
    const float* W     = (const float*)d_in[4];   // [NL][H][D][DH]
    const float* asrc  = (const float*)d_in[5];   // [NL][H][DH]
    const float* adst  = (const float*)d_in[6];
    const float* lns   = (const float*)d_in[7];   // [NL][D]
    const float* lnb   = (const float*)d_in[8];
    float* out = (float*)d_out;

    float* hA = (float*)sym_addr_hA();
    float* hB = (float*)sym_addr_hB();
    float* Wh = (float*)sym_addr_Wh();
    float* P  = (float*)sym_addr_P();
    float* Q  = (float*)sym_addr_Q();
    float* R  = (float*)sym_addr_R();
    float* S  = (float*)sym_addr_S();
    unsigned* mask = (unsigned*)sym_addr_mask();

    // node features + adjacency bitmask
    k_gather<<<BB * NN, 256>>>(nodes, emb, hA);
    k_mask<<<(BB * NN * NN) / 256, 256>>>(adj, mask);

    const int wstride = HH * DD * DHH;  // 65536
    const int astride = HH * DHH;       // 256

    // layer 0: hA -> hB
    k_gemm<<<(BB * NN) / 16, 256>>>(hA, W + 0 * wstride, Wh);
    k_srcdst<<<(BB * HH * NN) / 8, 256>>>(Wh, asrc + 0 * astride, adst + 0 * astride, P, Q, R, S);
    k_attn<<<(BB * NN) / 16, 256>>>(hA, Wh, P, Q, R, S, mask, lns + 0 * DD, lnb + 0 * DD, hB);

    // layer 1: hB -> out
    k_gemm<<<(BB * NN) / 16, 256>>>(hB, W + 1 * wstride, Wh);
    k_srcdst<<<(BB * HH * NN) / 8, 256>>>(Wh, asrc + 1 * astride, adst + 1 * astride, P, Q, R, S);
    k_attn<<<(BB * NN) / 16, 256>>>(hB, Wh, P, Q, R, S, mask, lns + 1 * DD, lnb + 1 * DD, out);

    // second tuple element (cfg_len) if the output buffer carries it
    if (out_size >= BB * NN * DD + BB)
        k_tail<<<1, 32>>>(clen, out);
}

// round 11
// speedup vs baseline: 1.0016x; 1.0016x over previous
#include <cuda_runtime.h>
#include <cstdint>

#define BB 8
#define NN 1024
#define LL 16
#define DD 256
#define HH 4
#define DHH 64
#define NLAYERS 2

// ---------------- scratch (global __device__ arrays; no allocs) ----------------
__device__ float g_hA[BB * NN * DD];
__device__ float g_hB[BB * NN * DD];
__device__ float g_Wh[BB * NN * DD];
__device__ float g_P[BB * HH * NN];
__device__ float g_Q[BB * HH * NN];
__device__ float g_R[BB * HH * NN];
__device__ float g_S[BB * HH * NN];
__device__ unsigned g_mask[BB * NN * (NN / 32)];

// ---------------- kernel 0: node features = mean of token embeddings ----------------
__global__ __launch_bounds__(256) void k_gather(const int* __restrict__ nodes,
                                                const float* __restrict__ emb,
                                                float* __restrict__ out) {
    int row = blockIdx.x;              // b*N + n
    int t = threadIdx.x;               // 0..255 = feature dim
    __shared__ int idx[LL];
    if (t < LL) idx[t] = nodes[(size_t)row * LL + t];
    __syncthreads();
    float acc = 0.f;
#pragma unroll
    for (int l = 0; l < LL; ++l)
        acc += emb[(size_t)idx[l] * DD + t];
    out[(size_t)row * DD + t] = acc * (1.0f / (float)LL);
}

// ---------------- kernel 1: adjacency (+self loop) -> bitmask ----------------
__global__ __launch_bounds__(256) void k_mask(const int* __restrict__ adj,
                                              unsigned* __restrict__ mask) {
    int gt = blockIdx.x * blockDim.x + threadIdx.x;
    int gw = gt >> 5;                  // word id in [0, B*N*32)
    int lane = gt & 31;
    int row = gw >> 5;                 // b*N + n
    int word = gw & 31;
    int n = row & (NN - 1);
    int m = word * 32 + lane;
    int v = adj[(size_t)row * NN + m];
    bool bit = (v != 0) || (m == n);
    unsigned w = __ballot_sync(0xffffffffu, bit);
    if (lane == 0) mask[gw] = w;
}

// ---------------- kernel 2: Wh = h @ W  (per layer) ----------------
// Wh layout: [b][n][c] with c = h*64+k (matches h_cat layout).
__global__ __launch_bounds__(256) void k_gemm(const float* __restrict__ h,
                                              const float* __restrict__ Wl,  // [H][D][DH]
                                              float* __restrict__ Wh) {
    __shared__ float hs[16][32];
    __shared__ float ws[32][256];
    int t = threadIdx.x;
    int row0 = blockIdx.x * 16;
    int c0 = (t & 63) * 4;
    int r0 = (t >> 6) * 4;
    float acc[4][4] = {};

    for (int d0 = 0; d0 < DD; d0 += 32) {
        {
            int e = t;
            hs[e >> 5][e & 31] = h[(size_t)(row0 + (e >> 5)) * DD + d0 + (e & 31)];
            e = t + 256;
            hs[e >> 5][e & 31] = h[(size_t)(row0 + (e >> 5)) * DD + d0 + (e & 31)];
        }
#pragma unroll
        for (int q = 0; q < 32; ++q) {
            int c = t;                 // dd = q, c = t (coalesced)
            int hh = c >> 6, k = c & 63;
            ws[q][c] = Wl[((size_t)hh * DD + (d0 + q)) * DHH + k];
        }
        __syncthreads();
#pragma unroll
        for (int dd = 0; dd < 32; ++dd) {
            float a0 = hs[r0 + 0][dd], a1 = hs[r0 + 1][dd];
            float a2 = hs[r0 + 2][dd], a3 = hs[r0 + 3][dd];
            float b0 = ws[dd][c0 + 0], b1 = ws[dd][c0 + 1];
            float b2 = ws[dd][c0 + 2], b3 = ws[dd][c0 + 3];
            acc[0][0] += a0 * b0; acc[0][1] += a0 * b1; acc[0][2] += a0 * b2; acc[0][3] += a0 * b3;
            acc[1][0] += a1 * b0; acc[1][1] += a1 * b1; acc[1][2] += a1 * b2; acc[1][3] += a1 * b3;
            acc[2][0] += a2 * b0; acc[2][1] += a2 * b1; acc[2][2] += a2 * b2; acc[2][3] += a2 * b3;
            acc[3][0] += a3 * b0; acc[3][1] += a3 * b1; acc[3][2] += a3 * b2; acc[3][3] += a3 * b3;
        }
        __syncthreads();
    }
#pragma unroll
    for (int i = 0; i < 4; ++i)
#pragma unroll
        for (int j = 0; j < 4; ++j)
            Wh[(size_t)(row0 + r0 + i) * DD + c0 + j] = acc[i][j];
}

// ---------------- kernel 3: src/dst dots + factorized exps ----------------
// P=exp(src), R=exp(0.2 src), Q=exp(dst), S=exp(0.2 dst), indexed [b][h][n].
__global__ __launch_bounds__(256) void k_srcdst(const float* __restrict__ Wh,
                                                const float* __restrict__ asrc,  // [H][DH]
                                                const float* __restrict__ adst,
                                                float* __restrict__ P, float* __restrict__ Q,
                                                float* __restrict__ R, float* __restrict__ S) {
    int gt = blockIdx.x * blockDim.x + threadIdx.x;
    int g = gt >> 5;                   // warp id = (b*H + h)*N + n
    int lane = gt & 31;
    int n = g & (NN - 1);
    int h = (g >> 10) & 3;
    int b = g >> 12;
    const float* whrow = Wh + ((size_t)(b * NN + n)) * DD + h * DHH;
    float x0 = whrow[lane], x1 = whrow[lane + 32];
    float s = x0 * asrc[h * DHH + lane] + x1 * asrc[h * DHH + lane + 32];
    float d = x0 * adst[h * DHH + lane] + x1 * adst[h * DHH + lane + 32];
#pragma unroll
    for (int o = 16; o; o >>= 1) {
        s += __shfl_down_sync(0xffffffffu, s, o);
        d += __shfl_down_sync(0xffffffffu, d, o);
    }
    if (lane == 0) {
        P[g] = __expf(s);
        R[g] = __expf(0.2f * s);
        Q[g] = __expf(d);
        S[g] = __expf(0.2f * d);
    }
}

// ---------------- kernel 4: fused masked-softmax attention + residual + LN ----------------
// CTA: 16 query rows, all 4 heads, all 256 output cols. m tiled by 32.
__global__ __launch_bounds__(256) void k_attn(const float* __restrict__ hin,
                                              const float* __restrict__ Wh,
                                              const float* __restrict__ P,
                                              const float* __restrict__ Qv,
                                              const float* __restrict__ R,
                                              const float* __restrict__ Sv,
                                              const unsigned* __restrict__ mask,
                                              const float* __restrict__ lns,
                                              const float* __restrict__ lnb,
                                              float* __restrict__ out) {
    __shared__ union {
        float whs[32][256];            // Wh m-tile (32 KB), reused as ybuf after m-loop
        float ybuf[16][256];
    } u;
    __shared__ float wsh[4][16][33];   // scores w[h][n][m_local], padded
    __shared__ float Ps[4][16], Rs[4][16];
    __shared__ float Qs[4][32], Ss[4][32];
    __shared__ unsigned mw[16];
    __shared__ float zpart[4][4][16];  // [mgroup][h][n]
    __shared__ float zs[4][16];

    int t = threadIdx.x;
    int b = blockIdx.x >> 6;           // 64 tiles per batch
    int row0 = (blockIdx.x & 63) * 16;

    // per-row P/R (once)
    if (t < 64) {
        int h = t >> 4, n = t & 15;
        int g = (b * HH + h) * NN + row0 + n;
        Ps[h][n] = P[g];
        Rs[h][n] = R[g];
    }

    // phase-A identity: (h, n) pair + m-subgroup
    int pa_h = (t >> 4) & 3, pa_n = t & 15, mg = t >> 6;
    float zacc = 0.f;
    // phase-B identity: 4 rows x 4 cols per thread
    int c0 = (t & 63) * 4, r0 = (t >> 6) * 4, hb = c0 >> 6;
    float acc[4][4] = {};

    for (int m0 = 0; m0 < NN; m0 += 32) {
        // stage Wh tile: 32 rows x 256 cols
#pragma unroll
        for (int q = 0; q < 32; ++q)
            u.whs[q][t] = Wh[((size_t)(b * NN + m0 + q)) * DD + t];
        // stage Q/S for this m tile
        if (t < 128) {
            int h = t >> 5, mm = t & 31;
            Qs[h][mm] = Qv[(b * HH + h) * NN + m0 + mm];
        } else {
            int tt = t - 128;
            int h = tt >> 5, mm = tt & 31;
            Ss[h][mm] = Sv[(b * HH + h) * NN + m0 + mm];
        }
        if (t < 16) mw[t] = mask[((size_t)(b * NN + row0 + t)) * 32 + (m0 >> 5)];
        __syncthreads();

        // phase A: scores w = mask * (P*Q >= 1 ? P*Q : R*S)
        {
            float pn = Ps[pa_h][pa_n], rn = Rs[pa_h][pa_n];
            unsigned mwn = mw[pa_n];
#pragma unroll
            for (int j = 0; j < 8; ++j) {
                int ml = mg * 8 + j;
                float pq = pn * Qs[pa_h][ml];
                float w = (pq >= 1.0f) ? pq : rn * Ss[pa_h][ml];
                w = ((mwn >> ml) & 1u) ? w : 0.f;
                zacc += w;
                wsh[pa_h][pa_n][ml] = w;
            }
        }
        __syncthreads();

        // phase B: acc += w @ Wh_tile  (4x4 register tile)
#pragma unroll
        for (int mm = 0; mm < 32; ++mm) {
            float w0 = wsh[hb][r0 + 0][mm];
            float w1 = wsh[hb][r0 + 1][mm];
            float w2 = wsh[hb][r0 + 2][mm];
            float w3 = wsh[hb][r0 + 3][mm];
            float4 bv = *(const float4*)&u.whs[mm][c0];
            acc[0][0] += w0 * bv.x; acc[0][1] += w0 * bv.y; acc[0][2] += w0 * bv.z; acc[0][3] += w0 * bv.w;
            acc[1][0] += w1 * bv.x; acc[1][1] += w1 * bv.y; acc[1][2] += w1 * bv.z; acc[1][3] += w1 * bv.w;
            acc[2][0] += w2 * bv.x; acc[2][1] += w2 * bv.y; acc[2][2] += w2 * bv.z; acc[2][3] += w2 * bv.w;
            acc[3][0] += w3 * bv.x; acc[3][1] += w3 * bv.y; acc[3][2] += w3 * bv.z; acc[3][3] += w3 * bv.w;
        }
        __syncthreads();
    }

    // reduce z partials (4 m-subgroups per (h,n))
    zpart[mg][pa_h][pa_n] = zacc;
    __syncthreads();
    if (t < 64) {
        int h = t >> 4, n = t & 15;
        zs[h][n] = zpart[0][h][n] + zpart[1][h][n] + zpart[2][h][n] + zpart[3][h][n];
    }
    __syncthreads();

    // epilogue: y = h_in + h_prime/z  -> smem
#pragma unroll
    for (int i = 0; i < 4; ++i) {
        float zinv = 1.0f / zs[hb][r0 + i];
        int r = r0 + i;
#pragma unroll
        for (int j = 0; j < 4; ++j) {
            int c = c0 + j;
            u.ybuf[r][c] = hin[((size_t)(b * NN + row0 + r)) * DD + c] + acc[i][j] * zinv;
        }
    }
    __syncthreads();

    // layernorm: 8 warps x 2 rows each
    int wid = t >> 5, lane = t & 31;
#pragma unroll
    for (int rr = 0; rr < 2; ++rr) {
        int r = wid * 2 + rr;
        float sum = 0.f, sq = 0.f;
        float vals[8];
#pragma unroll
        for (int q = 0; q < 8; ++q) {
            float v = u.ybuf[r][lane + q * 32];
            vals[q] = v;
            sum += v;
            sq += v * v;
        }
#pragma unroll
        for (int o = 16; o; o >>= 1) {
            sum += __shfl_xor_sync(0xffffffffu, sum, o);
            sq += __shfl_xor_sync(0xffffffffu, sq, o);
        }
        float mu = sum * (1.0f / (float)DD);
        float var = sq * (1.0f / (float)DD) - mu * mu;
        float rstd = rsqrtf(var + 1e-5f);
#pragma unroll
        for (int q = 0; q < 8; ++q) {
            int c = lane + q * 32;
            out[((size_t)(b * NN + row0 + r)) * DD + c] = (vals[q] - mu) * rstd * lns[c] + lnb[c];
        }
    }
}

// ---------------- tail: cfg_len passthrough as float ----------------
__global__ void k_tail(const int* __restrict__ clen, float* __restrict__ out) {
    int t = threadIdx.x;
    if (t < BB) out[(size_t)BB * NN * DD + t] = (float)clen[t];
}

// ---------------- host ----------------
static void* sym_addr_hA() { void* p; cudaGetSymbolAddress(&p, g_hA); return p; }
static void* sym_addr_hB() { void* p; cudaGetSymbolAddress(&p, g_hB); return p; }
static void* sym_addr_Wh() { void* p; cudaGetSymbolAddress(&p, g_Wh); return p; }
static void* sym_addr_P()  { void* p; cudaGetSymbolAddress(&p, g_P);  return p; }
static void* sym_addr_Q()  { void* p; cudaGetSymbolAddress(&p, g_Q);  return p; }
static void* sym_addr_R()  { void* p; cudaGetSymbolAddress(&p, g_R);  return p; }
static void* sym_addr_S()  { void* p; cudaGetSymbolAddress(&p, g_S);  return p; }
static void* sym_addr_mask() { void* p; cudaGetSymbolAddress(&p, g_mask); return p; }

extern "C" void kernel_launch(void* const* d_in, const int* in_sizes, int n_in,
                              void* d_out, int out_size) {
    const int*   adj   = (const int*)d_in[0];
    const int*   nodes = (const int*)d_in[1];
    const int*   clen  = (const int*)d_in[2];
    const float* emb   = (const float*)d_in[3];
    const float* W     = (const float*)d_in[4];   // [NL][H][D][DH]
    const float* asrc  = (const float*)d_in[5];   // [NL][H][DH]
    const float* adst  = (const float*)d_in[6];
    const float* lns   = (const float*)d_in[7];   // [NL][D]
    const float* lnb   = (const float*)d_in[8];
    float* out = (float*)d_out;

    float* hA = (float*)sym_addr_hA();
    float* hB = (float*)sym_addr_hB();
    float* Wh = (float*)sym_addr_Wh();
    float* P  = (float*)sym_addr_P();
    float* Q  = (float*)sym_addr_Q();
    float* R  = (float*)sym_addr_R();
    float* S  = (float*)sym_addr_S();
    unsigned* mask = (unsigned*)sym_addr_mask();

    // node features + adjacency bitmask
    k_gather<<<BB * NN, 256>>>(nodes, emb, hA);
    k_mask<<<(BB * NN * NN) / 256, 256>>>(adj, mask);

    const int wstride = HH * DD * DHH;  // 65536
    const int astride = HH * DHH;       // 256

    // layer 0: hA -> hB
    k_gemm<<<(BB * NN) / 16, 256>>>(hA, W + 0 * wstride, Wh);
    k_srcdst<<<(BB * HH * NN) / 8, 256>>>(Wh, asrc + 0 * astride, adst + 0 * astride, P, Q, R, S);
    k_attn<<<(BB * NN) / 16, 256>>>(hA, Wh, P, Q, R, S, mask, lns + 0 * DD, lnb + 0 * DD, hB);

    // layer 1: hB -> out
    k_gemm<<<(BB * NN) / 16, 256>>>(hB, W + 1 * wstride, Wh);
    k_srcdst<<<(BB * HH * NN) / 8, 256>>>(Wh, asrc + 1 * astride, adst + 1 * astride, P, Q, R, S);
    k_attn<<<(BB * NN) / 16, 256>>>(hB, Wh, P, Q, R, S, mask, lns + 1 * DD, lnb + 1 * DD, out);

    // second tuple element (cfg_len) if the output buffer carries it
    if (out_size >= BB * NN * DD + BB)
        k_tail<<<1, 32>>>(clen, out);
}